// round 16
// baseline (speedup 1.0000x reference)
#include <cuda_runtime.h>
#include <cuda_fp16.h>
#include <stdint.h>
#include <math.h>

// ---------------- problem constants ----------------
#define SS 2048
#define DD 4096
#define HH 32
#define QLORA 1536
#define KVLORA 512
#define ROPEW 64
#define NOPEW 128
#define QKH 192
#define VH 128
#define KEFF 576
#define NCOMB (QLORA + KEFF)   // 2112
#define EPSV 1e-6f
#define SCALE 0.07216878364870322f   // 1/sqrt(192)

typedef __half hf;

// ---------------- scratch ----------------
__device__ float g_qakv_f[(size_t)SS * NCOMB];
__device__ float g_scores[(size_t)HH * SS * SS];
__device__ hf g_hh[(size_t)SS * DD];               // hi only
__device__ hf g_wcomb_h[(size_t)NCOMB * DD];
__device__ hf g_wqb_h[(size_t)HH*QKH * QLORA];
__device__ hf g_wo_h[(size_t)DD * HH*VH];
__device__ hf g_wukt_h[(size_t)HH*KVLORA*NOPEW];
__device__ hf g_wuvt_h[(size_t)HH*VH*KVLORA];
__device__ hf g_qa_h[(size_t)SS * QLORA];          // hi only
__device__ hf g_q_h[(size_t)SS * HH*QKH];          // hi only
__device__ hf g_keff_h[(size_t)SS * KEFF];
__device__ hf g_kvct_h[(size_t)KVLORA * SS];
__device__ hf g_qeff_h[(size_t)HH*SS*KEFF];        // hi only
__device__ hf g_p_h[(size_t)HH*SS*SS];
__device__ hf g_ctxl_h[(size_t)HH*SS*KVLORA],   g_ctxl_l[(size_t)HH*SS*KVLORA];
__device__ hf g_ctx_h[(size_t)SS * HH*VH],      g_ctx_l[(size_t)SS * HH*VH];

// ---------------- helpers ----------------
__device__ __forceinline__ uint32_t smem_u32(const void* p) {
    uint32_t a;
    asm("{ .reg .u64 t; cvta.to.shared.u64 t, %1; cvt.u32.u64 %0, t; }" : "=r"(a) : "l"(p));
    return a;
}

__device__ __forceinline__ void hilo1(float v, hf& h, hf& l) {
    h = __float2half_rn(v);
    l = __float2half_rn(v - __half2float(h));
}
__device__ __forceinline__ void hilo2pack(float a, float b, uint32_t& h, uint32_t& l) {
    hf ha, hb2, la, lb;
    hilo1(a, ha, la); hilo1(b, hb2, lb);
    h = ((uint32_t)__half_as_ushort(hb2) << 16) | __half_as_ushort(ha);
    l = ((uint32_t)__half_as_ushort(lb) << 16) | __half_as_ushort(la);
}
__device__ __forceinline__ uint32_t hi2pack(float a, float b) {
    hf ha = __float2half_rn(a), hb = __float2half_rn(b);
    return ((uint32_t)__half_as_ushort(hb) << 16) | __half_as_ushort(ha);
}

__device__ __forceinline__ void mma_f16(float* c, const uint32_t* a, const uint32_t* b) {
    asm volatile(
        "mma.sync.aligned.m16n8k16.row.col.f32.f16.f16.f32 "
        "{%0,%1,%2,%3}, {%4,%5,%6,%7}, {%8,%9}, {%0,%1,%2,%3};"
        : "+f"(c[0]), "+f"(c[1]), "+f"(c[2]), "+f"(c[3])
        : "r"(a[0]), "r"(a[1]), "r"(a[2]), "r"(a[3]), "r"(b[0]), "r"(b[1]));
}

#define LDMX4(r0, r1, r2, r3, addr) \
    asm volatile("ldmatrix.sync.aligned.m8n8.x4.shared.b16 {%0,%1,%2,%3}, [%4];" \
        : "=r"(r0), "=r"(r1), "=r"(r2), "=r"(r3) : "r"(addr))

#define CPA16(dst, src, sz) \
    asm volatile("cp.async.cg.shared.global [%0], [%1], 16, %2;" \
        :: "r"(dst), "l"(src), "r"(sz))
#define CPA_COMMIT()  asm volatile("cp.async.commit_group;" ::: "memory")

// BK=64 chunks; rows of 72 hf (144B) -> conflict-free ldmatrix
#define BK   64
#define LDT  72
#define ARR_B   (128 * LDT * 2)      // 18432
#define GSMEM_U (6 * ARR_B)          // 110592

// ============================================================================
// NT GEMM: C = A * B^T. K-major fp16 operands. BK=64 chunks, single barrier.
// TERMS==2: Ah*Bh + Al*Bh  (2 stages)   TERMS==1: Ah*Bh  (3 stages)
// OUT: 0 = fp32 C, 1 = fp16 hi/lo (Ch,Cl), 2 = fp16 hi only (Ch)
// TRI: compacted lower-triangle grid.x.  CKEND: K limited to (bm+1)*128.
// Requires K % 64 == 0.
// ============================================================================
template<int TRI, int CKEND, int OUT, int TERMS>
__global__ void __launch_bounds__(256, 2)
hgemm(const hf* __restrict__ Ah, const hf* __restrict__ Al,
      const hf* __restrict__ Bh,
      float* __restrict__ C, hf* __restrict__ Ch, hf* __restrict__ Cl,
      int M, int N, int K, int lda, int ldb, int ldc,
      long long sA, long long sB, long long sC)
{
    constexpr int NARR = TERMS + 1;
    constexpr int CHUNK_B = NARR * ARR_B;
    constexpr int BARR = (TERMS == 2) ? 2 : 1;
    constexpr int S = (TERMS == 2) ? 2 : 3;      // pipeline stages

    int bm, bn;
    if (TRI) {
        int bi = blockIdx.x;
        bm = (int)((sqrtf(8.f * (float)bi + 1.f) - 1.f) * 0.5f);
        while ((bm + 1) * (bm + 2) / 2 <= bi) bm++;
        while (bm * (bm + 1) / 2 > bi) bm--;
        bn = bi - bm * (bm + 1) / 2;
        if (bn > bm) return;
    } else {
        bm = blockIdx.y; bn = blockIdx.x;
    }
    extern __shared__ char smem[];
    const uint32_t sbase = smem_u32(smem);

    const int tid = threadIdx.x, lane = tid & 31, wid = tid >> 5;
    const int wm = wid & 1, wn = wid >> 1;

    Ah += (long long)blockIdx.z * sA;
    if (TERMS == 2) Al += (long long)blockIdx.z * sA;
    Bh += (long long)blockIdx.z * sB;

    const int Kend = CKEND ? min(K, (bm + 1) * 128) : K;
    const int nch = Kend / BK;

    const int ch = tid & 7;
    const int rr = tid >> 3;
    const int ar0 = bm * 128 + rr;
    const int br0 = bn * 128 + rr;
    const hf* pAh = Ah + (long long)ar0 * lda + ch * 8;
    const hf* pAl = (TERMS == 2) ? Al + (long long)ar0 * lda + ch * 8 : nullptr;
    const uint32_t d0 = (uint32_t)(rr * (LDT * 2) + ch * 16);

    auto issue = [&](int slot, int k0) {
        uint32_t st = sbase + slot * CHUNK_B;
        #pragma unroll
        for (int p = 0; p < 4; p++) {
            uint32_t dd = d0 + p * (32 * LDT * 2);
            long long ro = (long long)(p * 32) * lda + k0;
            CPA16(st + 0 * ARR_B + dd, pAh + ro, 16u);
            if (TERMS == 2)
                CPA16(st + 1 * ARR_B + dd, pAl + ro, 16u);
            int brow = br0 + p * 32;
            uint32_t sz = (brow < N) ? 16u : 0u;
            const hf* pb = Bh + (long long)min(brow, N - 1) * ldb + ch * 8 + k0;
            CPA16(st + BARR * ARR_B + dd, pb, sz);
        }
    };

    const int arow_l = wm * 64 + ((lane >> 3) & 1) * 8 + (lane & 7);
    const int acol_l = (lane >> 4) * 8;
    const uint32_t aoff = (uint32_t)(arow_l * LDT + acol_l) * 2;
    const int brow_l = wn * 32 + ((lane >> 4) & 1) * 8 + (lane & 7);
    const int bcol_l = ((lane >> 3) & 1) * 8;
    const uint32_t boff = (uint32_t)(brow_l * LDT + bcol_l) * 2;
    const uint32_t MISTR = 16 * LDT * 2;   // 2304

    float acc[4][4][4];
    #pragma unroll
    for (int a = 0; a < 4; a++)
        #pragma unroll
        for (int b = 0; b < 4; b++)
            #pragma unroll
            for (int q = 0; q < 4; q++) acc[a][b][q] = 0.f;

    issue(0, 0); CPA_COMMIT();
    if (S == 3) {
        if (nch > 1) issue(1, BK);
        CPA_COMMIT();
    }

    for (int c = 0; c < nch; c++) {
        if (S == 2) asm volatile("cp.async.wait_group 0;" ::: "memory");
        else        asm volatile("cp.async.wait_group 1;" ::: "memory");
        __syncthreads();
        const int cn = c + S - 1;
        if (cn < nch) issue(cn % S, cn * BK);
        CPA_COMMIT();
        const uint32_t st = sbase + (c % S) * CHUNK_B;
        #pragma unroll
        for (int ks = 0; ks < 4; ks++) {
            const uint32_t kof = ks * 32;
            uint32_t ah[4][4], al[4][4], bh[4][2];
            #pragma unroll
            for (int mi = 0; mi < 4; mi++) {
                LDMX4(ah[mi][0], ah[mi][1], ah[mi][2], ah[mi][3],
                      st + 0 * ARR_B + aoff + mi * MISTR + kof);
                if (TERMS == 2)
                    LDMX4(al[mi][0], al[mi][1], al[mi][2], al[mi][3],
                          st + 1 * ARR_B + aoff + mi * MISTR + kof);
            }
            #pragma unroll
            for (int p = 0; p < 2; p++)
                LDMX4(bh[2*p][0], bh[2*p][1], bh[2*p+1][0], bh[2*p+1][1],
                      st + BARR * ARR_B + boff + p * MISTR + kof);
            #pragma unroll
            for (int mi = 0; mi < 4; mi++)
                #pragma unroll
                for (int ni = 0; ni < 4; ni++) {
                    mma_f16(acc[mi][ni], ah[mi], bh[ni]);
                    if (TERMS == 2) mma_f16(acc[mi][ni], al[mi], bh[ni]);
                }
        }
    }

    const int qr = lane >> 2, qc = lane & 3;
    if (OUT == 1) {
        hf* chp = Ch + (long long)blockIdx.z * sC;
        hf* clp = Cl + (long long)blockIdx.z * sC;
        #pragma unroll
        for (int mi = 0; mi < 4; mi++)
            #pragma unroll
            for (int ni = 0; ni < 4; ni++) {
                int r = bm * 128 + wm * 64 + mi * 16 + qr;
                int cc = bn * 128 + wn * 32 + ni * 8 + qc * 2;
                if (cc < N) {
                    uint32_t h0, l0, h1, l1;
                    hilo2pack(acc[mi][ni][0], acc[mi][ni][1], h0, l0);
                    hilo2pack(acc[mi][ni][2], acc[mi][ni][3], h1, l1);
                    *(uint32_t*)(chp + (long long)r * ldc + cc) = h0;
                    *(uint32_t*)(clp + (long long)r * ldc + cc) = l0;
                    *(uint32_t*)(chp + (long long)(r + 8) * ldc + cc) = h1;
                    *(uint32_t*)(clp + (long long)(r + 8) * ldc + cc) = l1;
                }
            }
    } else if (OUT == 2) {
        hf* chp = Ch + (long long)blockIdx.z * sC;
        #pragma unroll
        for (int mi = 0; mi < 4; mi++)
            #pragma unroll
            for (int ni = 0; ni < 4; ni++) {
                int r = bm * 128 + wm * 64 + mi * 16 + qr;
                int cc = bn * 128 + wn * 32 + ni * 8 + qc * 2;
                if (cc < N) {
                    *(uint32_t*)(chp + (long long)r * ldc + cc) =
                        hi2pack(acc[mi][ni][0], acc[mi][ni][1]);
                    *(uint32_t*)(chp + (long long)(r + 8) * ldc + cc) =
                        hi2pack(acc[mi][ni][2], acc[mi][ni][3]);
                }
            }
    } else {
        float* cp = C + (long long)blockIdx.z * sC;
        #pragma unroll
        for (int mi = 0; mi < 4; mi++)
            #pragma unroll
            for (int ni = 0; ni < 4; ni++) {
                int r = bm * 128 + wm * 64 + mi * 16 + qr;
                int cc = bn * 128 + wn * 32 + ni * 8 + qc * 2;
                if (cc < N) {
                    *(float2*)(cp + (long long)r * ldc + cc) =
                        make_float2(acc[mi][ni][0], acc[mi][ni][1]);
                    *(float2*)(cp + (long long)(r + 8) * ldc + cc) =
                        make_float2(acc[mi][ni][2], acc[mi][ni][3]);
                }
            }
    }
}

// ============================================================================
// conversion / elementwise kernels
// ============================================================================
__global__ void cvt_hi_k(const float* __restrict__ in, hf* __restrict__ oh, long long n)
{
    long long i = ((long long)blockIdx.x * 256 + threadIdx.x) * 4;
    if (i >= n) return;
    float4 v = *(const float4*)(in + i);
    uint2 h;
    hf h0 = __float2half_rn(v.x), h1 = __float2half_rn(v.y);
    hf h2 = __float2half_rn(v.z), h3 = __float2half_rn(v.w);
    h.x = ((uint32_t)__half_as_ushort(h1) << 16) | __half_as_ushort(h0);
    h.y = ((uint32_t)__half_as_ushort(h3) << 16) | __half_as_ushort(h2);
    *(uint2*)(oh + i) = h;
}

__global__ void cvt_hi_multi(const float* __restrict__ s0, hf* __restrict__ d0, long long n0,
                             const float* __restrict__ s1, hf* __restrict__ d1, long long n1,
                             const float* __restrict__ s2, hf* __restrict__ d2, long long n2,
                             const float* __restrict__ s3, hf* __restrict__ d3, long long n3,
                             int b1, int b2, int b3)
{
    int b = blockIdx.x;
    const float* s; hf* d; long long n; int lb;
    if (b < b1)      { s = s0; d = d0; n = n0; lb = b; }
    else if (b < b2) { s = s1; d = d1; n = n1; lb = b - b1; }
    else if (b < b3) { s = s2; d = d2; n = n2; lb = b - b2; }
    else             { s = s3; d = d3; n = n3; lb = b - b3; }
    long long i = ((long long)lb * 256 + threadIdx.x) * 4;
    if (i >= n) return;
    float4 v = *(const float4*)(s + i);
    uint2 h;
    hf h0 = __float2half_rn(v.x), h1 = __float2half_rn(v.y);
    hf h2 = __float2half_rn(v.z), h3 = __float2half_rn(v.w);
    h.x = ((uint32_t)__half_as_ushort(h1) << 16) | __half_as_ushort(h0);
    h.y = ((uint32_t)__half_as_ushort(h3) << 16) | __half_as_ushort(h2);
    *(uint2*)(d + i) = h;
}

__global__ void transcvt_hi_k(const float* __restrict__ in, hf* __restrict__ oh,
                              int ld_in, int ld_out, long long sIn, long long sOut)
{
    __shared__ float tile[32][33];
    const float* ip = in + (long long)blockIdx.z * sIn;
    int r0 = blockIdx.y * 32, c0 = blockIdx.x * 32;
    int tx = threadIdx.x & 31, ty = threadIdx.x >> 5;
    #pragma unroll
    for (int it = 0; it < 4; it++) {
        int r = ty + it * 8;
        tile[r][tx] = ip[(long long)(r0 + r) * ld_in + c0 + tx];
    }
    __syncthreads();
    #pragma unroll
    for (int it = 0; it < 4; it++) {
        int cr = ty + it * 8;
        long long o = (long long)blockIdx.z * sOut + (long long)(c0 + cr) * ld_out + r0 + tx;
        oh[o] = __float2half_rn(tile[tx][cr]);
    }
}

// rmsnorm over first n cols (row stride ldx) -> fp16 hi only
__global__ void rmsnorm_hi(const float* __restrict__ X, const float* __restrict__ g,
                           hf* __restrict__ oh, int n, int ldx)
{
    const float* x = X + (long long)blockIdx.x * ldx;
    hf* ph = oh + (long long)blockIdx.x * n;
    __shared__ float red[256];
    const int tid = threadIdx.x;
    float s = 0.f;
    for (int i = tid; i < n; i += 256) { float v = x[i]; s += v * v; }
    red[tid] = s; __syncthreads();
    for (int o = 128; o > 0; o >>= 1) {
        if (tid < o) red[tid] += red[tid + o];
        __syncthreads();
    }
    float inv = rsqrtf(red[0] / (float)n + EPSV);
    for (int i = tid; i < n; i += 256)
        ph[i] = __float2half_rn(x[i] * inv * g[i]);
}

__global__ void kv_post(float* __restrict__ KV, int ld, int off,
                        const float* __restrict__ g,
                        const float* __restrict__ cosb, const float* __restrict__ sinb,
                        hf* __restrict__ oh)
{
    const int srow = blockIdx.x;
    float* x = KV + (long long)srow * ld + off;
    hf* ph = oh + (long long)srow * KEFF;
    __shared__ float red[256];
    const int tid = threadIdx.x;
    float s = 0.f;
    for (int i = tid; i < KVLORA; i += 256) { float v = x[i]; s += v * v; }
    red[tid] = s; __syncthreads();
    for (int o = 128; o > 0; o >>= 1) {
        if (tid < o) red[tid] += red[tid + o];
        __syncthreads();
    }
    float inv = rsqrtf(red[0] / (float)KVLORA + EPSV);
    for (int i = tid; i < KVLORA; i += 256) x[i] = x[i] * inv * g[i];
    if (tid < 32) {
        float x1 = x[KVLORA + tid];
        float x2 = x[KVLORA + 32 + tid];
        float c1 = cosb[srow * ROPEW + tid];
        float c2 = cosb[srow * ROPEW + 32 + tid];
        float s1 = sinb[srow * ROPEW + tid];
        float s2 = sinb[srow * ROPEW + 32 + tid];
        x[KVLORA + tid]      = x1 * c1 - x2 * s1;
        x[KVLORA + 32 + tid] = x2 * c2 + x1 * s2;
    }
    __syncthreads();
    for (int i = tid; i < KEFF; i += 256)
        ph[i] = __float2half_rn(x[i]);
}

// q rope (q hi only) -> qeff hi only
__global__ void q_rope(const hf* __restrict__ Qh, hf* __restrict__ Eh,
                       const float* __restrict__ cosb, const float* __restrict__ sinb)
{
    long long idx = (long long)blockIdx.x * blockDim.x + threadIdx.x;
    const long long total = (long long)SS * HH * 32;
    if (idx >= total) return;
    int j  = (int)(idx & 31);
    long long sh = idx >> 5;
    int h = (int)(sh & (HH - 1));
    int s = (int)(sh >> 5);
    long long qb = ((long long)s * HH + h) * QKH + NOPEW;
    float x1 = __half2float(Qh[qb + j]);
    float x2 = __half2float(Qh[qb + j + 32]);
    float c1 = cosb[s * ROPEW + j];
    float c2 = cosb[s * ROPEW + 32 + j];
    float s1 = sinb[s * ROPEW + j];
    float s2 = sinb[s * ROPEW + 32 + j];
    long long ob = ((long long)h * SS + s) * KEFF + KVLORA;
    Eh[ob + j]      = __float2half_rn(x1 * c1 - x2 * s1);
    Eh[ob + j + 32] = __float2half_rn(x2 * c2 + x1 * s2);
}

__global__ void softmax_causal(const float* __restrict__ Sc, hf* __restrict__ Ph)
{
    __shared__ float4 buf4[SS / 4];
    __shared__ float red[256];
    float* buf = (float*)buf4;
    const int m = blockIdx.x;
    const int h = blockIdx.y;
    const float* row = Sc + ((long long)h * SS + m) * SS;
    hf* ph = Ph + ((long long)h * SS + m) * SS;
    const int len = m + 1;
    const int n4 = len >> 2;
    const int pad = ((m >> 7) + 1) << 7;
    const int tid = threadIdx.x;

    float mx = -3.4e38f;
    for (int i = tid; i < n4; i += 256) {
        float4 v = *(const float4*)(row + i * 4);
        buf4[i] = v;
        mx = fmaxf(fmaxf(mx, fmaxf(v.x, v.y)), fmaxf(v.z, v.w));
    }
    for (int i = n4 * 4 + tid; i < len; i += 256) {
        float v = row[i]; buf[i] = v; mx = fmaxf(mx, v);
    }
    red[tid] = mx; __syncthreads();
    for (int o = 128; o > 0; o >>= 1) {
        if (tid < o) red[tid] = fmaxf(red[tid], red[tid + o]);
        __syncthreads();
    }
    const float rowmax = red[0];
    __syncthreads();

    float sum = 0.f;
    for (int i = tid; i < n4; i += 256) {
        float4 v = buf4[i];
        v.x = __expf(SCALE * (v.x - rowmax));
        v.y = __expf(SCALE * (v.y - rowmax));
        v.z = __expf(SCALE * (v.z - rowmax));
        v.w = __expf(SCALE * (v.w - rowmax));
        buf4[i] = v;
        sum += (v.x + v.y) + (v.z + v.w);
    }
    for (int i = n4 * 4 + tid; i < len; i += 256) {
        float e = __expf(SCALE * (buf[i] - rowmax));
        buf[i] = e; sum += e;
    }
    red[tid] = sum; __syncthreads();
    for (int o = 128; o > 0; o >>= 1) {
        if (tid < o) red[tid] += red[tid + o];
        __syncthreads();
    }
    const float rinv = 1.f / red[0];
    for (int i = tid; i < n4; i += 256) {
        float4 v = buf4[i];
        hf a = __float2half_rn(v.x * rinv), b = __float2half_rn(v.y * rinv);
        hf c = __float2half_rn(v.z * rinv), d = __float2half_rn(v.w * rinv);
        uint2 o2;
        o2.x = ((uint32_t)__half_as_ushort(b) << 16) | __half_as_ushort(a);
        o2.y = ((uint32_t)__half_as_ushort(d) << 16) | __half_as_ushort(c);
        *(uint2*)(ph + i * 4) = o2;
    }
    for (int i = n4 * 4 + tid; i < len; i += 256)
        ph[i] = __float2half_rn(buf[i] * rinv);
    const hf z = __float2half(0.f);
    for (int i = len + tid; i < pad; i += 256) ph[i] = z;
}

// ============================================================================
extern "C" void kernel_launch(void* const* d_in, const int* in_sizes, int n_in,
                              void* d_out, int out_size)
{
    (void)in_sizes; (void)n_in; (void)out_size;
    const float* h      = (const float*)d_in[0];
    const float* cosb   = (const float*)d_in[1];
    const float* sinb   = (const float*)d_in[2];
    const float* w_q_a  = (const float*)d_in[3];
    const float* gq     = (const float*)d_in[4];
    const float* w_q_b  = (const float*)d_in[5];
    const float* w_kv_a = (const float*)d_in[6];
    const float* gkv    = (const float*)d_in[7];
    const float* w_uk   = (const float*)d_in[8];
    const float* w_uv   = (const float*)d_in[9];
    const float* w_o    = (const float*)d_in[10];
    float* out = (float*)d_out;

    float *qakv_f, *sc;
    hf *hh, *wcomb_h, *wqb_h, *wo_h, *wukt_h, *wuvt_h;
    hf *qa_h, *q_h, *keff_h, *kvct_h, *qeff_h;
    hf *p_h, *ctxl_h, *ctxl_l, *ctx_h, *ctx_l;
    cudaGetSymbolAddress((void**)&qakv_f, g_qakv_f);
    cudaGetSymbolAddress((void**)&sc,     g_scores);
    cudaGetSymbolAddress((void**)&hh,     g_hh);
    cudaGetSymbolAddress((void**)&wcomb_h, g_wcomb_h);
    cudaGetSymbolAddress((void**)&wqb_h,  g_wqb_h);
    cudaGetSymbolAddress((void**)&wo_h,   g_wo_h);
    cudaGetSymbolAddress((void**)&wukt_h, g_wukt_h);
    cudaGetSymbolAddress((void**)&wuvt_h, g_wuvt_h);
    cudaGetSymbolAddress((void**)&qa_h,   g_qa_h);
    cudaGetSymbolAddress((void**)&q_h,    g_q_h);
    cudaGetSymbolAddress((void**)&keff_h, g_keff_h);
    cudaGetSymbolAddress((void**)&kvct_h, g_kvct_h);
    cudaGetSymbolAddress((void**)&qeff_h, g_qeff_h);
    cudaGetSymbolAddress((void**)&p_h,    g_p_h);
    cudaGetSymbolAddress((void**)&ctxl_h, g_ctxl_h); cudaGetSymbolAddress((void**)&ctxl_l, g_ctxl_l);
    cudaGetSymbolAddress((void**)&ctx_h,  g_ctx_h);  cudaGetSymbolAddress((void**)&ctx_l,  g_ctx_l);

    cudaFuncSetAttribute(hgemm<0,0,0,1>, cudaFuncAttributeMaxDynamicSharedMemorySize, GSMEM_U);
    cudaFuncSetAttribute(hgemm<0,0,2,1>, cudaFuncAttributeMaxDynamicSharedMemorySize, GSMEM_U);
    cudaFuncSetAttribute(hgemm<1,0,0,1>, cudaFuncAttributeMaxDynamicSharedMemorySize, GSMEM_U);
    cudaFuncSetAttribute(hgemm<0,1,1,1>, cudaFuncAttributeMaxDynamicSharedMemorySize, GSMEM_U);
    cudaFuncSetAttribute(hgemm<0,0,1,2>, cudaFuncAttributeMaxDynamicSharedMemorySize, GSMEM_U);

    // --- operand conversions (all hi-only now) ---
    {
        long long n = (long long)SS * DD;
        cvt_hi_k<<<(unsigned)((n/4 + 255)/256), 256>>>(h, hh, n);
    }
    {
        long long n0 = (long long)QLORA * DD;
        long long n1 = (long long)KEFF * DD;
        long long n2 = (long long)HH * QKH * QLORA;
        long long n3 = (long long)DD * HH * VH;
        int c0 = (int)((n0/4 + 255)/256), c1 = (int)((n1/4 + 255)/256);
        int c2 = (int)((n2/4 + 255)/256), c3 = (int)((n3/4 + 255)/256);
        cvt_hi_multi<<<(unsigned)(c0 + c1 + c2 + c3), 256>>>(
            w_q_a,  wcomb_h,      n0,
            w_kv_a, wcomb_h + n0, n1,
            w_q_b,  wqb_h,        n2,
            w_o,    wo_h,         n3,
            c0, c0 + c1, c0 + c1 + c2);
    }
    transcvt_hi_k<<<dim3(KVLORA/32, NOPEW/32, HH), 256>>>(
        w_uk, wukt_h, KVLORA, NOPEW,
        (long long)NOPEW*KVLORA, (long long)KVLORA*NOPEW);
    transcvt_hi_k<<<dim3(VH/32, KVLORA/32, HH), 256>>>(
        w_uv, wuvt_h, VH, KVLORA,
        (long long)KVLORA*VH, (long long)VH*KVLORA);

    // 1) [q_a | kv] = h @ [w_q_a | w_kv_a]^T -> fp32 combined  (1-term)
    hgemm<0,0,0,1><<<dim3((NCOMB + 127)/128, SS/128, 1), 256, GSMEM_U>>>(
        hh, nullptr, wcomb_h, qakv_f, nullptr, nullptr,
        SS, NCOMB, DD, DD, DD, NCOMB, 0, 0, 0);
    // 2) rmsnorm(q_a cols) -> hi only
    rmsnorm_hi<<<SS, 256>>>(qakv_f, gq, qa_h, QLORA, NCOMB);
    // 3) q = q_a @ w_q_b^T -> hi only  (1-term)
    hgemm<0,0,2,1><<<dim3((HH*QKH)/128, SS/128, 1), 256, GSMEM_U>>>(
        qa_h, nullptr, wqb_h, nullptr, q_h, nullptr,
        SS, HH*QKH, QLORA, QLORA, QLORA, HH*QKH, 0, 0, 0);
    // 5) kv post: rmsnorm + rope -> keff hi
    kv_post<<<SS, 256>>>(qakv_f, NCOMB, QLORA, gkv, cosb, sinb, keff_h);
    // 5b) kv_c transpose -> kvct hi
    transcvt_hi_k<<<dim3(KVLORA/32, SS/32, 1), 256>>>(
        qakv_f + QLORA, kvct_h, NCOMB, SS, 0, 0);
    // 6) q_latent -> qeff[:, 0:512] hi only  (1-term)
    hgemm<0,0,2,1><<<dim3(KVLORA/128, SS/128, HH), 256, GSMEM_U>>>(
        q_h, nullptr, wukt_h, nullptr, qeff_h, nullptr,
        SS, KVLORA, NOPEW, HH*QKH, NOPEW, KEFF,
        (long long)QKH, (long long)KVLORA*NOPEW, (long long)SS*KEFF);
    // 7) q rope -> qeff[:, 512:576] hi only
    {
        long long total = (long long)SS * HH * 32;
        q_rope<<<(unsigned)((total + 255) / 256), 256>>>(q_h, qeff_h, cosb, sinb);
    }
    // 8) scores = qeff @ keff^T -> fp32  (1-term, triangle grid)
    {
        const int NT = SS / 128;
        const int NTRI = NT * (NT + 1) / 2;   // 136
        hgemm<1,0,0,1><<<dim3(NTRI, 1, HH), 256, GSMEM_U>>>(
            qeff_h, nullptr, keff_h, sc, nullptr, nullptr,
            SS, SS, KEFF, KEFF, KEFF, SS,
            (long long)SS*KEFF, 0, (long long)SS*SS);
    }
    // 9) causal softmax (vectorized) -> P hi only (+zero pad)
    softmax_causal<<<dim3(SS, HH), 256>>>(sc, p_h);
    // 10) ctx_latent = P @ kvct^T (K limited) -> hilo  (1-term)
    hgemm<0,1,1,1><<<dim3(KVLORA/128, SS/128, HH), 256, GSMEM_U>>>(
        p_h, nullptr, kvct_h, nullptr, ctxl_h, ctxl_l,
        SS, KVLORA, SS, SS, SS, KVLORA,
        (long long)SS*SS, 0, (long long)SS*KVLORA);
    // 11) ctx = ctxl @ wuvt^T -> hilo  (2-term)
    hgemm<0,0,1,2><<<dim3(1, SS/128, HH), 256, GSMEM_U>>>(
        ctxl_h, ctxl_l, wuvt_h, nullptr, ctx_h, ctx_l,
        SS, VH, KVLORA, KVLORA, KVLORA, HH*VH,
        (long long)SS*KVLORA, (long long)VH*KVLORA, (long long)VH);
    // 12) out = ctx @ w_o^T -> fp32  (1-term)
    hgemm<0,0,0,1><<<dim3(DD/128, SS/128, 1), 256, GSMEM_U>>>(
        ctx_h, nullptr, wo_h, out, nullptr, nullptr,
        SS, DD, HH*VH, HH*VH, HH*VH, DD, 0, 0, 0);
}

// round 17
// speedup vs baseline: 1.0671x; 1.0671x over previous
#include <cuda_runtime.h>
#include <cuda_fp16.h>
#include <stdint.h>
#include <math.h>

// ---------------- problem constants ----------------
#define SS 2048
#define DD 4096
#define HH 32
#define QLORA 1536
#define KVLORA 512
#define ROPEW 64
#define NOPEW 128
#define QKH 192
#define VH 128
#define KEFF 576
#define NCOMB (QLORA + KEFF)   // 2112
#define EPSV 1e-6f
#define SCALE 0.07216878364870322f   // 1/sqrt(192)

typedef __half hf;

// ---------------- scratch ----------------
__device__ float g_qakv_f[(size_t)SS * NCOMB];
__device__ hf g_sc_h[(size_t)HH * SS * SS];        // fp16 scores now
__device__ hf g_hh[(size_t)SS * DD];
__device__ hf g_wcomb_h[(size_t)NCOMB * DD];
__device__ hf g_wqb_h[(size_t)HH*QKH * QLORA];
__device__ hf g_wo_h[(size_t)DD * HH*VH];
__device__ hf g_wukt_h[(size_t)HH*KVLORA*NOPEW];
__device__ hf g_wuvt_h[(size_t)HH*VH*KVLORA];
__device__ hf g_qa_h[(size_t)SS * QLORA];
__device__ hf g_q_h[(size_t)SS * HH*QKH];
__device__ hf g_keff_h[(size_t)SS * KEFF];
__device__ hf g_kvct_h[(size_t)KVLORA * SS];
__device__ hf g_qeff_h[(size_t)HH*SS*KEFF];
__device__ hf g_p_h[(size_t)HH*SS*SS];
__device__ hf g_ctxl_h[(size_t)HH*SS*KVLORA];      // hi only
__device__ hf g_ctx_h[(size_t)SS * HH*VH];         // hi only

// ---------------- helpers ----------------
__device__ __forceinline__ uint32_t smem_u32(const void* p) {
    uint32_t a;
    asm("{ .reg .u64 t; cvta.to.shared.u64 t, %1; cvt.u32.u64 %0, t; }" : "=r"(a) : "l"(p));
    return a;
}

__device__ __forceinline__ void hilo1(float v, hf& h, hf& l) {
    h = __float2half_rn(v);
    l = __float2half_rn(v - __half2float(h));
}
__device__ __forceinline__ void hilo2pack(float a, float b, uint32_t& h, uint32_t& l) {
    hf ha, hb2, la, lb;
    hilo1(a, ha, la); hilo1(b, hb2, lb);
    h = ((uint32_t)__half_as_ushort(hb2) << 16) | __half_as_ushort(ha);
    l = ((uint32_t)__half_as_ushort(lb) << 16) | __half_as_ushort(la);
}
__device__ __forceinline__ uint32_t hi2pack(float a, float b) {
    hf ha = __float2half_rn(a), hb = __float2half_rn(b);
    return ((uint32_t)__half_as_ushort(hb) << 16) | __half_as_ushort(ha);
}

__device__ __forceinline__ void mma_f16(float* c, const uint32_t* a, const uint32_t* b) {
    asm volatile(
        "mma.sync.aligned.m16n8k16.row.col.f32.f16.f16.f32 "
        "{%0,%1,%2,%3}, {%4,%5,%6,%7}, {%8,%9}, {%0,%1,%2,%3};"
        : "+f"(c[0]), "+f"(c[1]), "+f"(c[2]), "+f"(c[3])
        : "r"(a[0]), "r"(a[1]), "r"(a[2]), "r"(a[3]), "r"(b[0]), "r"(b[1]));
}

#define LDMX4(r0, r1, r2, r3, addr) \
    asm volatile("ldmatrix.sync.aligned.m8n8.x4.shared.b16 {%0,%1,%2,%3}, [%4];" \
        : "=r"(r0), "=r"(r1), "=r"(r2), "=r"(r3) : "r"(addr))

#define CPA16(dst, src, sz) \
    asm volatile("cp.async.cg.shared.global [%0], [%1], 16, %2;" \
        :: "r"(dst), "l"(src), "r"(sz))
#define CPA_COMMIT()  asm volatile("cp.async.commit_group;" ::: "memory")

// BK=64 chunks; rows of 72 hf (144B) -> conflict-free ldmatrix
#define BK   64
#define LDT  72
#define ARR_B   (128 * LDT * 2)      // 18432
#define GSMEM_U (6 * ARR_B)          // 110592

// ============================================================================
// NT GEMM: C = A * B^T. K-major fp16 operands. BK=64 chunks, single barrier.
// TERMS==2: Ah*Bh + Al*Bh  (2 stages)   TERMS==1: Ah*Bh  (3 stages)
// OUT: 0 = fp32 C, 1 = fp16 hi/lo (Ch,Cl), 2 = fp16 hi only (Ch)
// TRI: compacted lower-triangle grid.x.  CKEND: K limited to (bm+1)*128.
// Requires K % 64 == 0.
// ============================================================================
template<int TRI, int CKEND, int OUT, int TERMS>
__global__ void __launch_bounds__(256, 2)
hgemm(const hf* __restrict__ Ah, const hf* __restrict__ Al,
      const hf* __restrict__ Bh,
      float* __restrict__ C, hf* __restrict__ Ch, hf* __restrict__ Cl,
      int M, int N, int K, int lda, int ldb, int ldc,
      long long sA, long long sB, long long sC)
{
    constexpr int NARR = TERMS + 1;
    constexpr int CHUNK_B = NARR * ARR_B;
    constexpr int BARR = (TERMS == 2) ? 2 : 1;
    constexpr int S = (TERMS == 2) ? 2 : 3;      // pipeline stages

    int bm, bn;
    if (TRI) {
        int bi = blockIdx.x;
        bm = (int)((sqrtf(8.f * (float)bi + 1.f) - 1.f) * 0.5f);
        while ((bm + 1) * (bm + 2) / 2 <= bi) bm++;
        while (bm * (bm + 1) / 2 > bi) bm--;
        bn = bi - bm * (bm + 1) / 2;
        if (bn > bm) return;
    } else {
        bm = blockIdx.y; bn = blockIdx.x;
    }
    extern __shared__ char smem[];
    const uint32_t sbase = smem_u32(smem);

    const int tid = threadIdx.x, lane = tid & 31, wid = tid >> 5;
    const int wm = wid & 1, wn = wid >> 1;

    Ah += (long long)blockIdx.z * sA;
    if (TERMS == 2) Al += (long long)blockIdx.z * sA;
    Bh += (long long)blockIdx.z * sB;

    const int Kend = CKEND ? min(K, (bm + 1) * 128) : K;
    const int nch = Kend / BK;

    const int ch = tid & 7;
    const int rr = tid >> 3;
    const int ar0 = bm * 128 + rr;
    const int br0 = bn * 128 + rr;
    const hf* pAh = Ah + (long long)ar0 * lda + ch * 8;
    const hf* pAl = (TERMS == 2) ? Al + (long long)ar0 * lda + ch * 8 : nullptr;
    const uint32_t d0 = (uint32_t)(rr * (LDT * 2) + ch * 16);

    auto issue = [&](int slot, int k0) {
        uint32_t st = sbase + slot * CHUNK_B;
        #pragma unroll
        for (int p = 0; p < 4; p++) {
            uint32_t dd = d0 + p * (32 * LDT * 2);
            long long ro = (long long)(p * 32) * lda + k0;
            CPA16(st + 0 * ARR_B + dd, pAh + ro, 16u);
            if (TERMS == 2)
                CPA16(st + 1 * ARR_B + dd, pAl + ro, 16u);
            int brow = br0 + p * 32;
            uint32_t sz = (brow < N) ? 16u : 0u;
            const hf* pb = Bh + (long long)min(brow, N - 1) * ldb + ch * 8 + k0;
            CPA16(st + BARR * ARR_B + dd, pb, sz);
        }
    };

    const int arow_l = wm * 64 + ((lane >> 3) & 1) * 8 + (lane & 7);
    const int acol_l = (lane >> 4) * 8;
    const uint32_t aoff = (uint32_t)(arow_l * LDT + acol_l) * 2;
    const int brow_l = wn * 32 + ((lane >> 4) & 1) * 8 + (lane & 7);
    const int bcol_l = ((lane >> 3) & 1) * 8;
    const uint32_t boff = (uint32_t)(brow_l * LDT + bcol_l) * 2;
    const uint32_t MISTR = 16 * LDT * 2;   // 2304

    float acc[4][4][4];
    #pragma unroll
    for (int a = 0; a < 4; a++)
        #pragma unroll
        for (int b = 0; b < 4; b++)
            #pragma unroll
            for (int q = 0; q < 4; q++) acc[a][b][q] = 0.f;

    issue(0, 0); CPA_COMMIT();
    if (S == 3) {
        if (nch > 1) issue(1, BK);
        CPA_COMMIT();
    }

    for (int c = 0; c < nch; c++) {
        if (S == 2) asm volatile("cp.async.wait_group 0;" ::: "memory");
        else        asm volatile("cp.async.wait_group 1;" ::: "memory");
        __syncthreads();
        const int cn = c + S - 1;
        if (cn < nch) issue(cn % S, cn * BK);
        CPA_COMMIT();
        const uint32_t st = sbase + (c % S) * CHUNK_B;
        #pragma unroll
        for (int ks = 0; ks < 4; ks++) {
            const uint32_t kof = ks * 32;
            uint32_t ah[4][4], al[4][4], bh[4][2];
            #pragma unroll
            for (int mi = 0; mi < 4; mi++) {
                LDMX4(ah[mi][0], ah[mi][1], ah[mi][2], ah[mi][3],
                      st + 0 * ARR_B + aoff + mi * MISTR + kof);
                if (TERMS == 2)
                    LDMX4(al[mi][0], al[mi][1], al[mi][2], al[mi][3],
                          st + 1 * ARR_B + aoff + mi * MISTR + kof);
            }
            #pragma unroll
            for (int p = 0; p < 2; p++)
                LDMX4(bh[2*p][0], bh[2*p][1], bh[2*p+1][0], bh[2*p+1][1],
                      st + BARR * ARR_B + boff + p * MISTR + kof);
            #pragma unroll
            for (int mi = 0; mi < 4; mi++)
                #pragma unroll
                for (int ni = 0; ni < 4; ni++) {
                    mma_f16(acc[mi][ni], ah[mi], bh[ni]);
                    if (TERMS == 2) mma_f16(acc[mi][ni], al[mi], bh[ni]);
                }
        }
    }

    const int qr = lane >> 2, qc = lane & 3;
    if (OUT == 1) {
        hf* chp = Ch + (long long)blockIdx.z * sC;
        hf* clp = Cl + (long long)blockIdx.z * sC;
        #pragma unroll
        for (int mi = 0; mi < 4; mi++)
            #pragma unroll
            for (int ni = 0; ni < 4; ni++) {
                int r = bm * 128 + wm * 64 + mi * 16 + qr;
                int cc = bn * 128 + wn * 32 + ni * 8 + qc * 2;
                if (cc < N) {
                    uint32_t h0, l0, h1, l1;
                    hilo2pack(acc[mi][ni][0], acc[mi][ni][1], h0, l0);
                    hilo2pack(acc[mi][ni][2], acc[mi][ni][3], h1, l1);
                    *(uint32_t*)(chp + (long long)r * ldc + cc) = h0;
                    *(uint32_t*)(clp + (long long)r * ldc + cc) = l0;
                    *(uint32_t*)(chp + (long long)(r + 8) * ldc + cc) = h1;
                    *(uint32_t*)(clp + (long long)(r + 8) * ldc + cc) = l1;
                }
            }
    } else if (OUT == 2) {
        hf* chp = Ch + (long long)blockIdx.z * sC;
        #pragma unroll
        for (int mi = 0; mi < 4; mi++)
            #pragma unroll
            for (int ni = 0; ni < 4; ni++) {
                int r = bm * 128 + wm * 64 + mi * 16 + qr;
                int cc = bn * 128 + wn * 32 + ni * 8 + qc * 2;
                if (cc < N) {
                    *(uint32_t*)(chp + (long long)r * ldc + cc) =
                        hi2pack(acc[mi][ni][0], acc[mi][ni][1]);
                    *(uint32_t*)(chp + (long long)(r + 8) * ldc + cc) =
                        hi2pack(acc[mi][ni][2], acc[mi][ni][3]);
                }
            }
    } else {
        float* cp = C + (long long)blockIdx.z * sC;
        #pragma unroll
        for (int mi = 0; mi < 4; mi++)
            #pragma unroll
            for (int ni = 0; ni < 4; ni++) {
                int r = bm * 128 + wm * 64 + mi * 16 + qr;
                int cc = bn * 128 + wn * 32 + ni * 8 + qc * 2;
                if (cc < N) {
                    *(float2*)(cp + (long long)r * ldc + cc) =
                        make_float2(acc[mi][ni][0], acc[mi][ni][1]);
                    *(float2*)(cp + (long long)(r + 8) * ldc + cc) =
                        make_float2(acc[mi][ni][2], acc[mi][ni][3]);
                }
            }
    }
}

// ============================================================================
// conversion / elementwise kernels
// ============================================================================
__global__ void cvt_hi_k(const float* __restrict__ in, hf* __restrict__ oh, long long n)
{
    long long i = ((long long)blockIdx.x * 256 + threadIdx.x) * 4;
    if (i >= n) return;
    float4 v = *(const float4*)(in + i);
    uint2 h;
    hf h0 = __float2half_rn(v.x), h1 = __float2half_rn(v.y);
    hf h2 = __float2half_rn(v.z), h3 = __float2half_rn(v.w);
    h.x = ((uint32_t)__half_as_ushort(h1) << 16) | __half_as_ushort(h0);
    h.y = ((uint32_t)__half_as_ushort(h3) << 16) | __half_as_ushort(h2);
    *(uint2*)(oh + i) = h;
}

__global__ void cvt_hi_multi(const float* __restrict__ s0, hf* __restrict__ d0, long long n0,
                             const float* __restrict__ s1, hf* __restrict__ d1, long long n1,
                             const float* __restrict__ s2, hf* __restrict__ d2, long long n2,
                             const float* __restrict__ s3, hf* __restrict__ d3, long long n3,
                             int b1, int b2, int b3)
{
    int b = blockIdx.x;
    const float* s; hf* d; long long n; int lb;
    if (b < b1)      { s = s0; d = d0; n = n0; lb = b; }
    else if (b < b2) { s = s1; d = d1; n = n1; lb = b - b1; }
    else if (b < b3) { s = s2; d = d2; n = n2; lb = b - b2; }
    else             { s = s3; d = d3; n = n3; lb = b - b3; }
    long long i = ((long long)lb * 256 + threadIdx.x) * 4;
    if (i >= n) return;
    float4 v = *(const float4*)(s + i);
    uint2 h;
    hf h0 = __float2half_rn(v.x), h1 = __float2half_rn(v.y);
    hf h2 = __float2half_rn(v.z), h3 = __float2half_rn(v.w);
    h.x = ((uint32_t)__half_as_ushort(h1) << 16) | __half_as_ushort(h0);
    h.y = ((uint32_t)__half_as_ushort(h3) << 16) | __half_as_ushort(h2);
    *(uint2*)(d + i) = h;
}

__global__ void transcvt_hi_k(const float* __restrict__ in, hf* __restrict__ oh,
                              int ld_in, int ld_out, long long sIn, long long sOut)
{
    __shared__ float tile[32][33];
    const float* ip = in + (long long)blockIdx.z * sIn;
    int r0 = blockIdx.y * 32, c0 = blockIdx.x * 32;
    int tx = threadIdx.x & 31, ty = threadIdx.x >> 5;
    #pragma unroll
    for (int it = 0; it < 4; it++) {
        int r = ty + it * 8;
        tile[r][tx] = ip[(long long)(r0 + r) * ld_in + c0 + tx];
    }
    __syncthreads();
    #pragma unroll
    for (int it = 0; it < 4; it++) {
        int cr = ty + it * 8;
        long long o = (long long)blockIdx.z * sOut + (long long)(c0 + cr) * ld_out + r0 + tx;
        oh[o] = __float2half_rn(tile[tx][cr]);
    }
}

// rmsnorm over first n cols (row stride ldx) -> fp16 hi only
__global__ void rmsnorm_hi(const float* __restrict__ X, const float* __restrict__ g,
                           hf* __restrict__ oh, int n, int ldx)
{
    const float* x = X + (long long)blockIdx.x * ldx;
    hf* ph = oh + (long long)blockIdx.x * n;
    __shared__ float red[256];
    const int tid = threadIdx.x;
    float s = 0.f;
    for (int i = tid; i < n; i += 256) { float v = x[i]; s += v * v; }
    red[tid] = s; __syncthreads();
    for (int o = 128; o > 0; o >>= 1) {
        if (tid < o) red[tid] += red[tid + o];
        __syncthreads();
    }
    float inv = rsqrtf(red[0] / (float)n + EPSV);
    for (int i = tid; i < n; i += 256)
        ph[i] = __float2half_rn(x[i] * inv * g[i]);
}

__global__ void kv_post(float* __restrict__ KV, int ld, int off,
                        const float* __restrict__ g,
                        const float* __restrict__ cosb, const float* __restrict__ sinb,
                        hf* __restrict__ oh)
{
    const int srow = blockIdx.x;
    float* x = KV + (long long)srow * ld + off;
    hf* ph = oh + (long long)srow * KEFF;
    __shared__ float red[256];
    const int tid = threadIdx.x;
    float s = 0.f;
    for (int i = tid; i < KVLORA; i += 256) { float v = x[i]; s += v * v; }
    red[tid] = s; __syncthreads();
    for (int o = 128; o > 0; o >>= 1) {
        if (tid < o) red[tid] += red[tid + o];
        __syncthreads();
    }
    float inv = rsqrtf(red[0] / (float)KVLORA + EPSV);
    for (int i = tid; i < KVLORA; i += 256) x[i] = x[i] * inv * g[i];
    if (tid < 32) {
        float x1 = x[KVLORA + tid];
        float x2 = x[KVLORA + 32 + tid];
        float c1 = cosb[srow * ROPEW + tid];
        float c2 = cosb[srow * ROPEW + 32 + tid];
        float s1 = sinb[srow * ROPEW + tid];
        float s2 = sinb[srow * ROPEW + 32 + tid];
        x[KVLORA + tid]      = x1 * c1 - x2 * s1;
        x[KVLORA + 32 + tid] = x2 * c2 + x1 * s2;
    }
    __syncthreads();
    for (int i = tid; i < KEFF; i += 256)
        ph[i] = __float2half_rn(x[i]);
}

// q rope (q hi only) -> qeff hi only
__global__ void q_rope(const hf* __restrict__ Qh, hf* __restrict__ Eh,
                       const float* __restrict__ cosb, const float* __restrict__ sinb)
{
    long long idx = (long long)blockIdx.x * blockDim.x + threadIdx.x;
    const long long total = (long long)SS * HH * 32;
    if (idx >= total) return;
    int j  = (int)(idx & 31);
    long long sh = idx >> 5;
    int h = (int)(sh & (HH - 1));
    int s = (int)(sh >> 5);
    long long qb = ((long long)s * HH + h) * QKH + NOPEW;
    float x1 = __half2float(Qh[qb + j]);
    float x2 = __half2float(Qh[qb + j + 32]);
    float c1 = cosb[s * ROPEW + j];
    float c2 = cosb[s * ROPEW + 32 + j];
    float s1 = sinb[s * ROPEW + j];
    float s2 = sinb[s * ROPEW + 32 + j];
    long long ob = ((long long)h * SS + s) * KEFF + KVLORA;
    Eh[ob + j]      = __float2half_rn(x1 * c1 - x2 * s1);
    Eh[ob + j + 32] = __float2half_rn(x2 * c2 + x1 * s2);
}

// causal softmax: fp16 scores in (uint2 = 4 halves), fp16 P out
__global__ void softmax_causal(const hf* __restrict__ Sc, hf* __restrict__ Ph)
{
    __shared__ float4 buf4[SS / 4];
    __shared__ float red[256];
    float* buf = (float*)buf4;
    const int m = blockIdx.x;
    const int h = blockIdx.y;
    const hf* row = Sc + ((long long)h * SS + m) * SS;
    hf* ph = Ph + ((long long)h * SS + m) * SS;
    const int len = m + 1;
    const int n4 = len >> 2;
    const int pad = ((m >> 7) + 1) << 7;
    const int tid = threadIdx.x;

    float mx = -3.4e38f;
    for (int i = tid; i < n4; i += 256) {
        uint2 u = *(const uint2*)(row + i * 4);
        float2 ab = __half22float2(*(const __half2*)&u.x);
        float2 cd = __half22float2(*(const __half2*)&u.y);
        buf4[i] = make_float4(ab.x, ab.y, cd.x, cd.y);
        mx = fmaxf(fmaxf(mx, fmaxf(ab.x, ab.y)), fmaxf(cd.x, cd.y));
    }
    for (int i = n4 * 4 + tid; i < len; i += 256) {
        float v = __half2float(row[i]); buf[i] = v; mx = fmaxf(mx, v);
    }
    red[tid] = mx; __syncthreads();
    for (int o = 128; o > 0; o >>= 1) {
        if (tid < o) red[tid] = fmaxf(red[tid], red[tid + o]);
        __syncthreads();
    }
    const float rowmax = red[0];
    __syncthreads();

    float sum = 0.f;
    for (int i = tid; i < n4; i += 256) {
        float4 v = buf4[i];
        v.x = __expf(SCALE * (v.x - rowmax));
        v.y = __expf(SCALE * (v.y - rowmax));
        v.z = __expf(SCALE * (v.z - rowmax));
        v.w = __expf(SCALE * (v.w - rowmax));
        buf4[i] = v;
        sum += (v.x + v.y) + (v.z + v.w);
    }
    for (int i = n4 * 4 + tid; i < len; i += 256) {
        float e = __expf(SCALE * (buf[i] - rowmax));
        buf[i] = e; sum += e;
    }
    red[tid] = sum; __syncthreads();
    for (int o = 128; o > 0; o >>= 1) {
        if (tid < o) red[tid] += red[tid + o];
        __syncthreads();
    }
    const float rinv = 1.f / red[0];
    for (int i = tid; i < n4; i += 256) {
        float4 v = buf4[i];
        hf a = __float2half_rn(v.x * rinv), b = __float2half_rn(v.y * rinv);
        hf c = __float2half_rn(v.z * rinv), d = __float2half_rn(v.w * rinv);
        uint2 o2;
        o2.x = ((uint32_t)__half_as_ushort(b) << 16) | __half_as_ushort(a);
        o2.y = ((uint32_t)__half_as_ushort(d) << 16) | __half_as_ushort(c);
        *(uint2*)(ph + i * 4) = o2;
    }
    for (int i = n4 * 4 + tid; i < len; i += 256)
        ph[i] = __float2half_rn(buf[i] * rinv);
    const hf z = __float2half(0.f);
    for (int i = len + tid; i < pad; i += 256) ph[i] = z;
}

// ============================================================================
extern "C" void kernel_launch(void* const* d_in, const int* in_sizes, int n_in,
                              void* d_out, int out_size)
{
    (void)in_sizes; (void)n_in; (void)out_size;
    const float* h      = (const float*)d_in[0];
    const float* cosb   = (const float*)d_in[1];
    const float* sinb   = (const float*)d_in[2];
    const float* w_q_a  = (const float*)d_in[3];
    const float* gq     = (const float*)d_in[4];
    const float* w_q_b  = (const float*)d_in[5];
    const float* w_kv_a = (const float*)d_in[6];
    const float* gkv    = (const float*)d_in[7];
    const float* w_uk   = (const float*)d_in[8];
    const float* w_uv   = (const float*)d_in[9];
    const float* w_o    = (const float*)d_in[10];
    float* out = (float*)d_out;

    float *qakv_f;
    hf *sc_h, *hh, *wcomb_h, *wqb_h, *wo_h, *wukt_h, *wuvt_h;
    hf *qa_h, *q_h, *keff_h, *kvct_h, *qeff_h;
    hf *p_h, *ctxl_h, *ctx_h;
    cudaGetSymbolAddress((void**)&qakv_f, g_qakv_f);
    cudaGetSymbolAddress((void**)&sc_h,   g_sc_h);
    cudaGetSymbolAddress((void**)&hh,     g_hh);
    cudaGetSymbolAddress((void**)&wcomb_h, g_wcomb_h);
    cudaGetSymbolAddress((void**)&wqb_h,  g_wqb_h);
    cudaGetSymbolAddress((void**)&wo_h,   g_wo_h);
    cudaGetSymbolAddress((void**)&wukt_h, g_wukt_h);
    cudaGetSymbolAddress((void**)&wuvt_h, g_wuvt_h);
    cudaGetSymbolAddress((void**)&qa_h,   g_qa_h);
    cudaGetSymbolAddress((void**)&q_h,    g_q_h);
    cudaGetSymbolAddress((void**)&keff_h, g_keff_h);
    cudaGetSymbolAddress((void**)&kvct_h, g_kvct_h);
    cudaGetSymbolAddress((void**)&qeff_h, g_qeff_h);
    cudaGetSymbolAddress((void**)&p_h,    g_p_h);
    cudaGetSymbolAddress((void**)&ctxl_h, g_ctxl_h);
    cudaGetSymbolAddress((void**)&ctx_h,  g_ctx_h);

    cudaFuncSetAttribute(hgemm<0,0,0,1>, cudaFuncAttributeMaxDynamicSharedMemorySize, GSMEM_U);
    cudaFuncSetAttribute(hgemm<0,0,2,1>, cudaFuncAttributeMaxDynamicSharedMemorySize, GSMEM_U);
    cudaFuncSetAttribute(hgemm<1,0,2,1>, cudaFuncAttributeMaxDynamicSharedMemorySize, GSMEM_U);
    cudaFuncSetAttribute(hgemm<0,1,2,1>, cudaFuncAttributeMaxDynamicSharedMemorySize, GSMEM_U);

    // --- operand conversions (all hi-only) ---
    {
        long long n = (long long)SS * DD;
        cvt_hi_k<<<(unsigned)((n/4 + 255)/256), 256>>>(h, hh, n);
    }
    {
        long long n0 = (long long)QLORA * DD;
        long long n1 = (long long)KEFF * DD;
        long long n2 = (long long)HH * QKH * QLORA;
        long long n3 = (long long)DD * HH * VH;
        int c0 = (int)((n0/4 + 255)/256), c1 = (int)((n1/4 + 255)/256);
        int c2 = (int)((n2/4 + 255)/256), c3 = (int)((n3/4 + 255)/256);
        cvt_hi_multi<<<(unsigned)(c0 + c1 + c2 + c3), 256>>>(
            w_q_a,  wcomb_h,      n0,
            w_kv_a, wcomb_h + n0, n1,
            w_q_b,  wqb_h,        n2,
            w_o,    wo_h,         n3,
            c0, c0 + c1, c0 + c1 + c2);
    }
    transcvt_hi_k<<<dim3(KVLORA/32, NOPEW/32, HH), 256>>>(
        w_uk, wukt_h, KVLORA, NOPEW,
        (long long)NOPEW*KVLORA, (long long)KVLORA*NOPEW);
    transcvt_hi_k<<<dim3(VH/32, KVLORA/32, HH), 256>>>(
        w_uv, wuvt_h, VH, KVLORA,
        (long long)KVLORA*VH, (long long)VH*KVLORA);

    // 1) [q_a | kv] = h @ [w_q_a | w_kv_a]^T -> fp32 combined  (1-term)
    hgemm<0,0,0,1><<<dim3((NCOMB + 127)/128, SS/128, 1), 256, GSMEM_U>>>(
        hh, nullptr, wcomb_h, qakv_f, nullptr, nullptr,
        SS, NCOMB, DD, DD, DD, NCOMB, 0, 0, 0);
    // 2) rmsnorm(q_a cols) -> hi only
    rmsnorm_hi<<<SS, 256>>>(qakv_f, gq, qa_h, QLORA, NCOMB);
    // 3) q = q_a @ w_q_b^T -> hi only  (1-term)
    hgemm<0,0,2,1><<<dim3((HH*QKH)/128, SS/128, 1), 256, GSMEM_U>>>(
        qa_h, nullptr, wqb_h, nullptr, q_h, nullptr,
        SS, HH*QKH, QLORA, QLORA, QLORA, HH*QKH, 0, 0, 0);
    // 5) kv post: rmsnorm + rope -> keff hi
    kv_post<<<SS, 256>>>(qakv_f, NCOMB, QLORA, gkv, cosb, sinb, keff_h);
    // 5b) kv_c transpose -> kvct hi
    transcvt_hi_k<<<dim3(KVLORA/32, SS/32, 1), 256>>>(
        qakv_f + QLORA, kvct_h, NCOMB, SS, 0, 0);
    // 6) q_latent -> qeff[:, 0:512] hi only  (1-term)
    hgemm<0,0,2,1><<<dim3(KVLORA/128, SS/128, HH), 256, GSMEM_U>>>(
        q_h, nullptr, wukt_h, nullptr, qeff_h, nullptr,
        SS, KVLORA, NOPEW, HH*QKH, NOPEW, KEFF,
        (long long)QKH, (long long)KVLORA*NOPEW, (long long)SS*KEFF);
    // 7) q rope -> qeff[:, 512:576] hi only
    {
        long long total = (long long)SS * HH * 32;
        q_rope<<<(unsigned)((total + 255) / 256), 256>>>(q_h, qeff_h, cosb, sinb);
    }
    // 8) scores = qeff @ keff^T -> fp16 hi  (1-term, triangle grid)
    {
        const int NT = SS / 128;
        const int NTRI = NT * (NT + 1) / 2;   // 136
        hgemm<1,0,2,1><<<dim3(NTRI, 1, HH), 256, GSMEM_U>>>(
            qeff_h, nullptr, keff_h, nullptr, sc_h, nullptr,
            SS, SS, KEFF, KEFF, KEFF, SS,
            (long long)SS*KEFF, 0, (long long)SS*SS);
    }
    // 9) causal softmax (fp16 in/out, vectorized) -> P hi (+zero pad)
    softmax_causal<<<dim3(SS, HH), 256>>>(sc_h, p_h);
    // 10) ctx_latent = P @ kvct^T (K limited) -> hi only  (1-term)
    hgemm<0,1,2,1><<<dim3(KVLORA/128, SS/128, HH), 256, GSMEM_U>>>(
        p_h, nullptr, kvct_h, nullptr, ctxl_h, nullptr,
        SS, KVLORA, SS, SS, SS, KVLORA,
        (long long)SS*SS, 0, (long long)SS*KVLORA);
    // 11) ctx = ctxl @ wuvt^T -> hi only  (1-term)
    hgemm<0,0,2,1><<<dim3(1, SS/128, HH), 256, GSMEM_U>>>(
        ctxl_h, nullptr, wuvt_h, nullptr, ctx_h, nullptr,
        SS, VH, KVLORA, KVLORA, KVLORA, HH*VH,
        (long long)SS*KVLORA, (long long)VH*KVLORA, (long long)VH);
    // 12) out = ctx @ w_o^T -> fp32  (1-term)
    hgemm<0,0,0,1><<<dim3(DD/128, SS/128, 1), 256, GSMEM_U>>>(
        ctx_h, nullptr, wo_h, out, nullptr, nullptr,
        SS, DD, HH*VH, HH*VH, HH*VH, DD, 0, 0, 0);
}